// round 1
// baseline (speedup 1.0000x reference)
#include <cuda_runtime.h>
#include <math.h>

#define NB 4
#define NS 1024
#define ND 1024
#define NH 16
#define HD 64
#define NFF 4096
#define NR (NB*NS)   // 4096 rows

// ---------------- scratch arena (compile-time offsets, no allocation) --------
constexpr long long OFF_XN   = 0;
constexpr long long OFF_WQKV = OFF_XN   + (long long)NR*(ND+1);        // packed QKV weight (1025 x 3072)
constexpr long long OFF_BQKV = OFF_WQKV + (long long)(ND+1)*3*ND;
constexpr long long OFF_QKV  = OFF_BQKV + 3*ND;
constexpr long long OFF_Q    = OFF_QKV  + (long long)NR*3*ND;
constexpr long long OFF_K    = OFF_Q    + (long long)NB*NH*NS*(HD+1);
constexpr long long OFF_V    = OFF_K    + (long long)NB*NH*NS*(HD+1);
constexpr long long OFF_CAT  = OFF_V    + (long long)NB*NH*NS*(HD+1);
constexpr long long OFF_AO   = OFF_CAT  + (long long)NR*NH*(HD+1);
constexpr long long OFF_X1   = OFF_AO   + (long long)NR*ND;
constexpr long long OFF_H2   = OFF_X1   + (long long)NR*(ND+1);
constexpr long long OFF_HG   = OFF_H2   + (long long)NR*(ND+1);
constexpr long long OFF_MLP  = OFF_HG   + (long long)NR*(NFF+1);
constexpr long long SCRATCH_TOTAL = OFF_MLP + (long long)NR*ND;

__device__ __align__(256) float g_scratch[SCRATCH_TOTAL];

// ---------------- reductions -------------------------------------------------
__device__ __forceinline__ float warp_sum(float v) {
    v += __shfl_xor_sync(0xffffffffu, v, 16);
    v += __shfl_xor_sync(0xffffffffu, v, 8);
    v += __shfl_xor_sync(0xffffffffu, v, 4);
    v += __shfl_xor_sync(0xffffffffu, v, 2);
    v += __shfl_xor_sync(0xffffffffu, v, 1);
    return v;
}

// 256-thread block sum
__device__ __forceinline__ float block_sum(float v, float* sbuf) {
    __syncthreads();
    v = warp_sum(v);
    if ((threadIdx.x & 31) == 0) sbuf[threadIdx.x >> 5] = v;
    __syncthreads();
    if (threadIdx.x < 32) {
        float r = (threadIdx.x < 8) ? sbuf[threadIdx.x] : 0.f;
        r = warp_sum(r);
        if (threadIdx.x == 0) sbuf[0] = r;
    }
    __syncthreads();
    return sbuf[0];
}

// ---------------- weight repack: [Wq|Wk|Wv](h,d,e) -> (d, 3*1024) ------------
__global__ void repack_kernel(const float* __restrict__ Wq, const float* __restrict__ Wk,
                              const float* __restrict__ Wv, const float* __restrict__ bq,
                              const float* __restrict__ bk, const float* __restrict__ bv) {
    long long idx = (long long)blockIdx.x * 256 + threadIdx.x;
    const long long tot = (long long)(ND+1) * 3 * ND;
    if (idx < tot) {
        int col = (int)(idx % (3*ND));
        int d   = (int)(idx / (3*ND));
        int which = col >> 10;
        int rem   = col & 1023;
        int h = rem >> 6, e = rem & 63;
        const float* W = (which == 0) ? Wq : (which == 1 ? Wk : Wv);
        g_scratch[OFF_WQKV + idx] = W[((long long)h*(ND+1) + d)*HD + e];
    }
    if (idx < 3*ND) {
        int col = (int)idx;
        int which = col >> 10;
        int rem   = col & 1023;
        const float* bp = (which == 0) ? bq : (which == 1 ? bk : bv);
        g_scratch[OFF_BQKV + col] = bp[rem];
    }
}

// ---------------- hyperbolic layernorm + to_manifold -------------------------
__global__ __launch_bounds__(256) void ln_kernel(const float* __restrict__ Xext, long long xoff,
                                                 const float* __restrict__ g, const float* __restrict__ bb,
                                                 long long ooff) {
    const float* X = Xext ? Xext : (g_scratch + xoff);
    float* O = g_scratch + ooff;
    __shared__ float sbuf[8];
    int row = blockIdx.x, tid = threadIdx.x;
    const float* xr = X + (long long)row*(ND+1) + 1;
    float v[4]; float s = 0.f;
    #pragma unroll
    for (int i = 0; i < 4; i++) { v[i] = xr[tid + i*256]; s += v[i]; }
    float mu = block_sum(s, sbuf) * (1.f/ND);
    float vs = 0.f;
    #pragma unroll
    for (int i = 0; i < 4; i++) { float d = v[i]-mu; vs += d*d; }
    float var = block_sum(vs, sbuf) * (1.f/ND);
    float rstd = rsqrtf(var + 1e-5f);
    float y[4]; float ss = 0.f;
    #pragma unroll
    for (int i = 0; i < 4; i++) {
        int c = tid + i*256;
        y[i] = (v[i]-mu)*rstd*g[c] + bb[c];
        ss += y[i]*y[i];
    }
    float tot = block_sum(ss, sbuf);
    float* orow = O + (long long)row*(ND+1);
    if (tid == 0) orow[0] = sqrtf(tot + 1.f);
    #pragma unroll
    for (int i = 0; i < 4; i++) orow[1 + tid + i*256] = y[i];
}

// ---------------- generic SGEMM: C(M,N) = A(M,K)@B(K,N) + bias [opt GELU] ----
__device__ __forceinline__ float gelu_tanh(float c) {
    float u = 0.7978845608028654f * (c + 0.044715f*c*c*c);
    return 0.5f * c * (1.f + tanhf(u));
}

template<bool GELU>
__global__ __launch_bounds__(256) void sgemm_kernel(long long aoff,
        const float* __restrict__ Bext, long long boff,
        const float* __restrict__ biasext, long long biasoff,
        long long coff, int M, int N, int K, int ldc, int ccol) {
    const float* A    = g_scratch + aoff;
    const float* Bp   = Bext    ? Bext    : (g_scratch + boff);
    const float* bias = biasext ? biasext : (g_scratch + biasoff);
    float* C = g_scratch + coff;
    __shared__ float As[8][128];
    __shared__ float Bs[8][128];
    int tid = threadIdx.x;
    int tx = tid & 15, ty = tid >> 4;
    int row0 = blockIdx.y * 128, col0 = blockIdx.x * 128;
    float acc[8][8];
    #pragma unroll
    for (int i = 0; i < 8; i++)
        #pragma unroll
        for (int j = 0; j < 8; j++) acc[i][j] = 0.f;
    int a_row = tid >> 1, a_colb = (tid & 1) << 2;
    int b_row = tid >> 5, b_colb = (tid & 31) << 2;
    const float* Ab = A + (long long)row0 * K;
    for (int k0 = 0; k0 < K; k0 += 8) {
        #pragma unroll
        for (int i = 0; i < 4; i++) {
            int kk = k0 + a_colb + i;
            As[a_colb+i][a_row] = (kk < K) ? Ab[(long long)a_row*K + kk] : 0.f;
        }
        int kb = k0 + b_row;
        if (kb < K) {
            const float4 bv4 = *reinterpret_cast<const float4*>(Bp + (long long)kb*N + col0 + b_colb);
            Bs[b_row][b_colb+0] = bv4.x; Bs[b_row][b_colb+1] = bv4.y;
            Bs[b_row][b_colb+2] = bv4.z; Bs[b_row][b_colb+3] = bv4.w;
        } else {
            Bs[b_row][b_colb+0] = 0.f; Bs[b_row][b_colb+1] = 0.f;
            Bs[b_row][b_colb+2] = 0.f; Bs[b_row][b_colb+3] = 0.f;
        }
        __syncthreads();
        #pragma unroll
        for (int k = 0; k < 8; k++) {
            float ar[8], br[8];
            #pragma unroll
            for (int i = 0; i < 8; i++) ar[i] = As[k][ty*8+i];
            #pragma unroll
            for (int j = 0; j < 8; j++) br[j] = Bs[k][tx*8+j];
            #pragma unroll
            for (int i = 0; i < 8; i++)
                #pragma unroll
                for (int j = 0; j < 8; j++) acc[i][j] += ar[i]*br[j];
        }
        __syncthreads();
    }
    #pragma unroll
    for (int i = 0; i < 8; i++) {
        int m = row0 + ty*8 + i;
        float* crow = C + (long long)m*ldc + ccol + col0;
        #pragma unroll
        for (int j = 0; j < 8; j++) {
            int n = col0 + tx*8 + j;
            float c = acc[i][j] + bias[n];
            if (GELU) c = gelu_tanh(c);
            crow[tx*8 + j] = c;
        }
    }
}

// ---------------- QKV post: RoPE + L2-normalize(q,k) + to_manifold -----------
// one warp per (b,s,h); lane handles e=lane and e=lane+32
__global__ __launch_bounds__(256) void qkvpost_kernel(const float* __restrict__ rc,
                                                      const float* __restrict__ rs) {
    int w    = (blockIdx.x << 3) + (threadIdx.x >> 5);
    int lane = threadIdx.x & 31;
    int h = w & (NH-1);
    int s = (w >> 4) & (NS-1);
    int b = w >> 14;
    const float* qkv = g_scratch + OFF_QKV + (long long)(b*NS + s)*3*ND + h*HD;
    float c0 = rc[s*32 + (lane>>1)],      s0 = rs[s*32 + (lane>>1)];
    float c1 = rc[s*32 + 16 + (lane>>1)], s1 = rs[s*32 + 16 + (lane>>1)];
    bool even = (lane & 1) == 0;
    long long dst = (long long)((b*NH + h)*NS + s)*(HD+1);

    #pragma unroll
    for (int which = 0; which < 2; which++) {  // 0=q, 1=k
        float v0 = qkv[which*ND + lane], v1 = qkv[which*ND + lane + 32];
        float p0 = __shfl_xor_sync(0xffffffffu, v0, 1);
        float p1 = __shfl_xor_sync(0xffffffffu, v1, 1);
        float r0 = even ? (v0*c0 - p0*s0) : (p0*s0 + v0*c0);
        float r1 = even ? (v1*c1 - p1*s1) : (p1*s1 + v1*c1);
        float ssum = warp_sum(r0*r0 + r1*r1);
        float rn = rsqrtf(ssum + 1e-6f);
        r0 *= rn; r1 *= rn;
        float t = sqrtf(ssum*rn*rn + 1.f);
        float* dp = g_scratch + (which == 0 ? OFF_Q : OFF_K) + dst;
        if (lane == 0) dp[0] = t;
        dp[1+lane] = r0; dp[33+lane] = r1;
    }
    {   // v: manifold only
        float v0 = qkv[2*ND + lane], v1 = qkv[2*ND + lane + 32];
        float ssum = warp_sum(v0*v0 + v1*v1);
        float* dp = g_scratch + OFF_V + dst;
        if (lane == 0) dp[0] = sqrtf(ssum + 1.f);
        dp[1+lane] = v0; dp[33+lane] = v1;
    }
}

// ---------------- fused flash attention + project + concat -------------------
// grid(16, 64): x = query tile (64 q), y = b*H+h. 256 thr: 4 parts per query.
__global__ __launch_bounds__(256) void attn_kernel(const float* __restrict__ scale_p,
                                                   const float* __restrict__ bias_p) {
    __shared__ float Qs[64][65];
    __shared__ float KVs[65][68];  // transposed [dim][key], 68 keeps 16B align for float4
    int bh = blockIdx.y;
    int qt = blockIdx.x;
    int b = bh >> 4, h = bh & 15;
    float inv_scale = 1.f / *scale_p;
    float abias = *bias_p;
    int tid = threadIdx.x;
    int ql = tid >> 2, part = tid & 3;
    const float* Qb = g_scratch + OFF_Q + ((long long)bh*NS + qt*64)*65;
    const float* Kb = g_scratch + OFF_K + (long long)bh*NS*65;
    const float* Vb = g_scratch + OFF_V + (long long)bh*NS*65;
    for (int idx = tid; idx < 64*65; idx += 256) {
        int r = idx/65, c = idx%65;
        float v = Qb[idx];
        Qs[r][c] = (c == 0) ? -v : v;   // fold Lorentz sign into q time component
    }
    float acc[65];
    #pragma unroll
    for (int d = 0; d < 65; d++) acc[d] = 0.f;
    float mi = -1e30f, li = 0.f;
    for (int kt = 0; kt < 16; kt++) {
        __syncthreads();
        for (int idx = tid; idx < 64*65; idx += 256) {
            int r = idx/65, c = idx%65;
            KVs[c][r] = Kb[(long long)kt*64*65 + idx];
        }
        __syncthreads();
        float sc[16];
        #pragma unroll
        for (int jj = 0; jj < 16; jj++) sc[jj] = 0.f;
        #pragma unroll 1
        for (int c = 0; c < 65; c++) {
            float qv = Qs[ql][c];
            #pragma unroll
            for (int jj = 0; jj < 16; jj++) sc[jj] += qv * KVs[c][part*16 + jj];
        }
        float tmax = -1e30f;
        #pragma unroll
        for (int jj = 0; jj < 16; jj++) {
            sc[jj] = (2.f + 2.f*sc[jj])*inv_scale + abias;
            tmax = fmaxf(tmax, sc[jj]);
        }
        tmax = fmaxf(tmax, __shfl_xor_sync(0xffffffffu, tmax, 1));
        tmax = fmaxf(tmax, __shfl_xor_sync(0xffffffffu, tmax, 2));
        float mnew = fmaxf(mi, tmax);
        float corr = __expf(mi - mnew);
        float ps = 0.f;
        #pragma unroll
        for (int jj = 0; jj < 16; jj++) { sc[jj] = __expf(sc[jj]-mnew); ps += sc[jj]; }
        ps += __shfl_xor_sync(0xffffffffu, ps, 1);
        ps += __shfl_xor_sync(0xffffffffu, ps, 2);
        li = li*corr + ps;
        mi = mnew;
        __syncthreads();
        for (int idx = tid; idx < 64*65; idx += 256) {
            int r = idx/65, c = idx%65;
            KVs[c][r] = Vb[(long long)kt*64*65 + idx];
        }
        __syncthreads();
        #pragma unroll
        for (int d = 0; d < 65; d++) {
            float a = acc[d]*corr;
            #pragma unroll
            for (int jj = 0; jj < 16; jj++) a += sc[jj]*KVs[d][part*16 + jj];
            acc[d] = a;
        }
    }
    // combine the 4 key-partitions
    #pragma unroll
    for (int d = 0; d < 65; d++) {
        acc[d] += __shfl_xor_sync(0xffffffffu, acc[d], 1);
        acc[d] += __shfl_xor_sync(0xffffffffu, acc[d], 2);
    }
    float invl = 1.f/li;
    float m0 = acc[0]*invl;
    float ssq = 0.f;
    #pragma unroll
    for (int d = 1; d < 65; d++) { float md = acc[d]*invl; ssq += md*md; }
    float inv = invl * rsqrtf(fmaxf(m0*m0 - ssq, 1e-6f));  // project
    int sg = qt*64 + ql;
    float* dstp = g_scratch + OFF_CAT + (long long)(b*NS + sg)*(NH*(HD+1)) + h*(HD+1);
    for (int d = part; d < 65; d += 4) dstp[d] = acc[d]*inv;
}

// ---------------- residual + Lorentz projection ------------------------------
__global__ __launch_bounds__(256) void resproj_kernel(const float* __restrict__ Xext, long long xoff,
                                                      long long doff, const float* __restrict__ wptr,
                                                      float* Oext, long long ooff) {
    const float* X   = Xext ? Xext : (g_scratch + xoff);
    const float* Dsp = g_scratch + doff;
    float* O = Oext ? Oext : (g_scratch + ooff);
    __shared__ float sbuf[8];
    int row = blockIdx.x, tid = threadIdx.x;
    float w = *wptr;
    const float* dr = Dsp + (long long)row*ND;
    const float* xr = X + (long long)row*(ND+1);
    float d[4]; float s = 0.f;
    #pragma unroll
    for (int i = 0; i < 4; i++) { d[i] = dr[tid + i*256]; s += d[i]*d[i]; }
    float td = sqrtf(block_sum(s, sbuf) + 1.f);   // to_manifold time of delta
    float z0 = xr[0] + w*td;
    float z[4]; float zs = 0.f;
    #pragma unroll
    for (int i = 0; i < 4; i++) { z[i] = xr[1 + tid + i*256] + w*d[i]; zs += z[i]*z[i]; }
    float tot = block_sum(zs, sbuf);
    float inv = rsqrtf(fmaxf(z0*z0 - tot, 1e-6f));
    float* orow = O + (long long)row*(ND+1);
    if (tid == 0) orow[0] = z0*inv;
    #pragma unroll
    for (int i = 0; i < 4; i++) orow[1 + tid + i*256] = z[i]*inv;
}

// ---------------- time component of gelu'd hidden (col 0 of HG buffer) -------
__global__ __launch_bounds__(256) void hgtime_kernel() {
    __shared__ float sbuf[8];
    int row = blockIdx.x, tid = threadIdx.x;
    float* hr = g_scratch + OFF_HG + (long long)row*(NFF+1);
    float s = 0.f;
    for (int c = tid; c < NFF; c += 256) { float v = hr[1+c]; s += v*v; }
    float tot = block_sum(s, sbuf);
    if (tid == 0) hr[0] = sqrtf(tot + 1.f);
}

// ---------------- launch ------------------------------------------------------
extern "C" void kernel_launch(void* const* d_in, const int* in_sizes, int n_in,
                              void* d_out, int out_size) {
    const float* x      = (const float*)d_in[0];
    const float* rc     = (const float*)d_in[1];
    const float* rs     = (const float*)d_in[2];
    const float* n1g    = (const float*)d_in[3];
    const float* n1b    = (const float*)d_in[4];
    const float* Wq     = (const float*)d_in[5];
    const float* bq     = (const float*)d_in[6];
    const float* Wk     = (const float*)d_in[7];
    const float* bk     = (const float*)d_in[8];
    const float* Wv     = (const float*)d_in[9];
    const float* bv     = (const float*)d_in[10];
    const float* ascale = (const float*)d_in[11];
    const float* abias  = (const float*)d_in[12];
    const float* Wo     = (const float*)d_in[13];
    const float* bo     = (const float*)d_in[14];
    const float* wr1    = (const float*)d_in[15];
    const float* n2g    = (const float*)d_in[16];
    const float* n2b    = (const float*)d_in[17];
    const float* W1     = (const float*)d_in[18];
    const float* b1     = (const float*)d_in[19];
    const float* W2     = (const float*)d_in[20];
    const float* b2     = (const float*)d_in[21];
    const float* wr2    = (const float*)d_in[22];
    float* out = (float*)d_out;

    // 1. repack QKV weights+bias into one (1025 x 3072) matrix
    {
        long long tot = (long long)(ND+1)*3*ND;
        int blocks = (int)((tot + 255)/256);
        repack_kernel<<<blocks, 256>>>(Wq, Wk, Wv, bq, bk, bv);
    }
    // 2. hyperbolic layernorm 1: x -> xn
    ln_kernel<<<NR, 256>>>(x, 0, n1g, n1b, OFF_XN);
    // 3. QKV GEMM: xn(4096,1025) @ Wqkv(1025,3072) + b
    sgemm_kernel<false><<<dim3(3072/128, NR/128), 256>>>(OFF_XN, nullptr, OFF_WQKV,
            nullptr, OFF_BQKV, OFF_QKV, NR, 3072, ND+1, 3072, 0);
    // 4. RoPE + normalize + to_manifold -> Q/K/V (b,h,s,65)
    qkvpost_kernel<<<NB*NS*NH/8, 256>>>(rc, rs);
    // 5. fused flash attention + project -> cat (4096,1040)
    attn_kernel<<<dim3(NS/64, NB*NH), 256>>>(ascale, abias);
    // 6. Wo GEMM: cat(4096,1040) @ Wo(1040,1024) + bo -> attn spatial
    sgemm_kernel<false><<<dim3(ND/128, NR/128), 256>>>(OFF_CAT, Wo, 0,
            bo, 0, OFF_AO, NR, ND, NH*(HD+1), ND, 0);
    // 7. x1 = project(x + w1 * to_manifold(attn))
    resproj_kernel<<<NR, 256>>>(x, 0, OFF_AO, wr1, nullptr, OFF_X1);
    // 8. hyperbolic layernorm 2: x1 -> h2
    ln_kernel<<<NR, 256>>>(nullptr, OFF_X1, n2g, n2b, OFF_H2);
    // 9. W1 GEMM + GELU: h2(4096,1025) @ W1(1025,4096) -> hg cols 1..4096
    sgemm_kernel<true><<<dim3(NFF/128, NR/128), 256>>>(OFF_H2, W1, 0,
            b1, 0, OFF_HG, NR, NFF, ND+1, NFF+1, 1);
    // 10. time component of gelu'd hidden -> hg col 0
    hgtime_kernel<<<NR, 256>>>();
    // 11. W2 GEMM: hg(4096,4097) @ W2(4097,1024) + b2 -> mlp spatial
    sgemm_kernel<false><<<dim3(ND/128, NR/128), 256>>>(OFF_HG, W2, 0,
            b2, 0, OFF_MLP, NR, ND, NFF+1, ND, 0);
    // 12. out = project(x1 + w2 * to_manifold(mlp))
    resproj_kernel<<<NR, 256>>>(nullptr, OFF_X1, OFF_MLP, wr2, out, 0);
}

// round 6
// speedup vs baseline: 1.6176x; 1.6176x over previous
#include <cuda_runtime.h>
#include <cuda_bf16.h>
#include <math.h>
#include <stdint.h>

#define NB 4
#define NS 1024
#define ND 1024
#define NH 16
#define HD 64
#define NFF 4096
#define NR (NB*NS)   // 4096 rows

// ---------------- fp32 scratch arena ----------------------------------------
constexpr long long OFF_XN   = 0;
constexpr long long OFF_BQKV = OFF_XN   + (long long)NR*(ND+1);
constexpr long long OFF_QKV  = OFF_BQKV + 3*ND;
constexpr long long OFF_Q    = OFF_QKV  + (long long)NR*3*ND;
constexpr long long OFF_K    = OFF_Q    + (long long)NB*NH*NS*(HD+1);
constexpr long long OFF_V    = OFF_K    + (long long)NB*NH*NS*(HD+1);
constexpr long long OFF_CAT  = OFF_V    + (long long)NB*NH*NS*(HD+1);
constexpr long long OFF_AO   = OFF_CAT  + (long long)NR*NH*(HD+1);
constexpr long long OFF_X1   = OFF_AO   + (long long)NR*ND;
constexpr long long OFF_H2   = OFF_X1   + (long long)NR*(ND+1);
constexpr long long OFF_HG   = OFF_H2   + (long long)NR*(ND+1);
constexpr long long OFF_MLP  = OFF_HG   + (long long)NR*(NFF+1);
constexpr long long SCRATCH_TOTAL = OFF_MLP + (long long)NR*ND;

__device__ __align__(256) float g_scratch[SCRATCH_TOTAL];

// ---------------- bf16 hi/lo arenas for tensor-core GEMMs -------------------
constexpr long long A_ELE = 4096LL*4160;   // biggest A: HG (4096 x 4160)
constexpr long long B_ELE = 4096LL*1088;   // biggest B: W1^T (4096 x 1088)
__device__ __align__(256) __nv_bfloat16 g_AH[A_ELE];
__device__ __align__(256) __nv_bfloat16 g_AL[A_ELE];
__device__ __align__(256) __nv_bfloat16 g_BH[B_ELE];
__device__ __align__(256) __nv_bfloat16 g_BL[B_ELE];

// ---------------- PTX helpers ------------------------------------------------
__device__ __forceinline__ uint32_t smem_u32(const void* p) {
    uint32_t a;
    asm("{ .reg .u64 t; cvta.to.shared.u64 t, %1; cvt.u32.u64 %0, t; }" : "=r"(a) : "l"(p));
    return a;
}
#define CP_ASYNC16(dst, src) asm volatile("cp.async.cg.shared.global [%0], [%1], 16;" :: "r"(dst), "l"(src) : "memory")
#define CP_COMMIT()          asm volatile("cp.async.commit_group;" ::: "memory")
#define CP_WAIT(n)           asm volatile("cp.async.wait_group %0;" :: "n"(n) : "memory")

#define MMA_BF16(acc, a, b) \
    asm volatile("mma.sync.aligned.m16n8k16.row.col.f32.bf16.bf16.f32 " \
                 "{%0,%1,%2,%3},{%4,%5,%6,%7},{%8,%9},{%0,%1,%2,%3};" \
                 : "+f"((acc)[0]), "+f"((acc)[1]), "+f"((acc)[2]), "+f"((acc)[3]) \
                 : "r"((a)[0]), "r"((a)[1]), "r"((a)[2]), "r"((a)[3]), \
                   "r"((b)[0]), "r"((b)[1]))

// ---------------- reductions -------------------------------------------------
__device__ __forceinline__ float warp_sum(float v) {
    v += __shfl_xor_sync(0xffffffffu, v, 16);
    v += __shfl_xor_sync(0xffffffffu, v, 8);
    v += __shfl_xor_sync(0xffffffffu, v, 4);
    v += __shfl_xor_sync(0xffffffffu, v, 2);
    v += __shfl_xor_sync(0xffffffffu, v, 1);
    return v;
}
__device__ __forceinline__ float block_sum(float v, float* sbuf) {
    __syncthreads();
    v = warp_sum(v);
    if ((threadIdx.x & 31) == 0) sbuf[threadIdx.x >> 5] = v;
    __syncthreads();
    if (threadIdx.x < 32) {
        float r = (threadIdx.x < 8) ? sbuf[threadIdx.x] : 0.f;
        r = warp_sum(r);
        if (threadIdx.x == 0) sbuf[0] = r;
    }
    __syncthreads();
    return sbuf[0];
}

// ---------------- bias pack for fused QKV ------------------------------------
__global__ void biaspack_kernel(const float* __restrict__ bq, const float* __restrict__ bk,
                                const float* __restrict__ bv) {
    int col = blockIdx.x*256 + threadIdx.x;
    if (col < 3*ND) {
        int which = col >> 10, rem = col & 1023;
        const float* bp = (which == 0) ? bq : (which == 1 ? bk : bv);
        g_scratch[OFF_BQKV + col] = bp[rem];
    }
}

// ---------------- A-side conversion: fp32 [4096,Ksrc] -> bf16 hi/lo [4096,Kp]
__global__ __launch_bounds__(256) void convA_kernel(long long srcoff, int Ksrc, int Kp) {
    long long idx = (long long)blockIdx.x*256 + threadIdx.x;
    long long tot = 4096LL*Kp;
    if (idx >= tot) return;
    int k = (int)(idx % Kp);
    long long m = idx / Kp;
    float v = (k < Ksrc) ? g_scratch[srcoff + m*Ksrc + k] : 0.f;
    __nv_bfloat16 hi = __float2bfloat16_rn(v);
    __nv_bfloat16 lo = __float2bfloat16_rn(v - __bfloat162float(hi));
    g_AH[idx] = hi; g_AL[idx] = lo;
}

// ---------------- B transpose+convert: fp32 [Ksrc,N] -> bf16 hi/lo [N,Kp] ----
__global__ __launch_bounds__(256) void convT_kernel(const float* __restrict__ src,
                                                    int Ksrc, int N, int Kp) {
    __shared__ float tile[32][33];
    int tx = threadIdx.x, ty = threadIdx.y;           // block (32,8)
    int n0 = blockIdx.x*32, k0 = blockIdx.y*32;
    #pragma unroll
    for (int i = 0; i < 4; i++) {
        int k = k0 + ty + i*8;
        tile[ty + i*8][tx] = (k < Ksrc) ? src[(long long)k*N + n0 + tx] : 0.f;
    }
    __syncthreads();
    #pragma unroll
    for (int i = 0; i < 4; i++) {
        int n = n0 + ty + i*8;
        int k = k0 + tx;
        float v = tile[tx][ty + i*8];
        __nv_bfloat16 hi = __float2bfloat16_rn(v);
        __nv_bfloat16 lo = __float2bfloat16_rn(v - __bfloat162float(hi));
        long long di = (long long)n*Kp + k;
        g_BH[di] = hi; g_BL[di] = lo;
    }
}

// ---------------- fused QKV weight transpose ---------------------------------
__global__ __launch_bounds__(256) void convQKV_kernel(const float* __restrict__ Wq,
                                                      const float* __restrict__ Wk,
                                                      const float* __restrict__ Wv) {
    __shared__ float tile[32][33];
    int tx = threadIdx.x, ty = threadIdx.y;
    int e0 = blockIdx.x*32, k0 = blockIdx.y*32;
    int z = blockIdx.z;            // which*16 + h
    int which = z >> 4, h = z & 15;
    const float* W = (which == 0) ? Wq : (which == 1 ? Wk : Wv);
    #pragma unroll
    for (int i = 0; i < 4; i++) {
        int k = k0 + ty + i*8;
        tile[ty + i*8][tx] = (k < ND+1) ? W[((long long)h*(ND+1) + k)*HD + e0 + tx] : 0.f;
    }
    __syncthreads();
    #pragma unroll
    for (int i = 0; i < 4; i++) {
        int e = e0 + ty + i*8;
        int k = k0 + tx;
        float v = tile[tx][ty + i*8];
        __nv_bfloat16 hi = __float2bfloat16_rn(v);
        __nv_bfloat16 lo = __float2bfloat16_rn(v - __bfloat162float(hi));
        int n = which*1024 + h*64 + e;
        long long di = (long long)n*1088 + k;
        g_BH[di] = hi; g_BL[di] = lo;
    }
}

// ---------------- HMMA GEMM: C(4096,N) = A @ B^T, bf16x3 split ---------------
// 128x128 tile, 8 warps (2x4), warp tile 64x32, K-chunk 64, cp.async dbl-buf.
__device__ __forceinline__ float gelu_tanh(float c) {
    float u = 0.7978845608028654f * (c + 0.044715f*c*c*c);
    return 0.5f * c * (1.f + tanhf(u));
}

template<bool GELU>
__global__ __launch_bounds__(256, 1)
void mma_gemm_kernel(const float* __restrict__ biasext, long long biasoff,
                     long long coff, int Kp, int ldc, int ccol) {
    extern __shared__ char sm[];
    const int tid = threadIdx.x;
    const int wid = tid >> 5, lane = tid & 31;
    const int warp_m = wid & 1, warp_n = wid >> 1;
    const int row0 = blockIdx.y * 128, col0 = blockIdx.x * 128;
    const uint32_t sbase = smem_u32(sm);

    float acc[4][4][4];
    #pragma unroll
    for (int i = 0; i < 4; i++)
        #pragma unroll
        for (int j = 0; j < 4; j++)
            #pragma unroll
            for (int q = 0; q < 4; q++) acc[i][j][q] = 0.f;

    const int nchunk = Kp >> 6;

    // ---- chunk loader: 4 tiles of 128 rows x 128 bytes, SW128 swizzle ----
    auto load_chunk = [&](int c, int bi) {
        const long long k0 = (long long)c << 6;
        uint32_t base = sbase + (uint32_t)bi * 65536u;
        #pragma unroll
        for (int t = 0; t < 4; t++) {
            int id = t*256 + tid;
            int r = id >> 3, s = id & 7;
            uint32_t off = (uint32_t)(r*128 + s*16);
            uint32_t sw  = off ^ ((off >> 3) & 0x70u);
            long long ai = (long long)(row0 + r)*Kp + k0 + s*8;
            long long bj = (long long)(col0 + r)*Kp + k0 + s*8;
            CP_ASYNC16(base + sw,           g_AH + ai);
            CP_ASYNC16(base + 16384u + sw,  g_AL + ai);
            CP_ASYNC16(base + 32768u + sw,  g_BH + bj);
            CP_ASYNC16(base + 49152u + sw,  g_BL + bj);
        }
    };

    // per-lane constant addressing pieces
    const uint32_t kmask = (uint32_t)(((lane >> 2) & 7) << 4);
    const uint32_t lrow  = (uint32_t)(lane >> 2);
    const uint32_t lkb   = (uint32_t)((lane & 3) * 4);

    auto compute = [&](int bi) {
        const char* Ah = sm + bi*65536;
        const char* Al = Ah + 16384;
        const char* Bh = Ah + 32768;
        const char* Bl = Ah + 49152;
        #pragma unroll
        for (int k16 = 0; k16 < 4; k16++) {
            uint32_t kb  = (uint32_t)(k16*32) + lkb;
            uint32_t ka0 = kb ^ kmask;
            uint32_t ka2 = (kb + 16u) ^ kmask;
            uint32_t ahf[4][4], alf[4][4], bhf[4][2], blf[4][2];
            #pragma unroll
            for (int tm = 0; tm < 4; tm++) {
                uint32_t r = (uint32_t)(warp_m*64 + tm*16) + lrow;
                uint32_t a0 = r*128 + ka0, a2 = r*128 + ka2;
                ahf[tm][0] = *(const uint32_t*)(Ah + a0);
                ahf[tm][1] = *(const uint32_t*)(Ah + a0 + 1024);
                ahf[tm][2] = *(const uint32_t*)(Ah + a2);
                ahf[tm][3] = *(const uint32_t*)(Ah + a2 + 1024);
                alf[tm][0] = *(const uint32_t*)(Al + a0);
                alf[tm][1] = *(const uint32_t*)(Al + a0 + 1024);
                alf[tm][2] = *(const uint32_t*)(Al + a2);
                alf[tm][3] = *(const uint32_t*)(Al + a2 + 1024);
            }
            #pragma unroll
            for (int tn = 0; tn < 4; tn++) {
                uint32_t n = (uint32_t)(warp_n*32 + tn*8) + lrow;
                uint32_t b0 = n*128 + ka0, b2 = n*128 + ka2;
                bhf[tn][0] = *(const uint32_t*)(Bh + b0);
                bhf[tn][1] = *(const uint32_t*)(Bh + b2);
                blf[tn][0] = *(const uint32_t*)(Bl + b0);
                blf[tn][1] = *(const uint32_t*)(Bl + b2);
            }
            #pragma unroll
            for (int tm = 0; tm < 4; tm++)
                #pragma unroll
                for (int tn = 0; tn < 4; tn++) {
                    MMA_BF16(acc[tm][tn], ahf[tm], bhf[tn]);
                    MMA_BF16(acc[tm][tn], ahf[tm], blf[tn]);
                    MMA_BF16(acc[tm][tn], alf[tm], bhf[tn]);
                }
        }
    };

    load_chunk(0, 0); CP_COMMIT();
    for (int c = 0; c < nchunk; c++) {
        int bi = c & 1;
        if (c + 1 < nchunk) { load_chunk(c + 1, bi ^ 1); CP_COMMIT(); CP_WAIT(1); }
        else                { CP_WAIT(0); }
        __syncthreads();
        compute(bi);
        __syncthreads();
    }

    // ---- epilogue ----
    const float* bias = biasext ? biasext : (g_scratch + biasoff);
    #pragma unroll
    for (int tm = 0; tm < 4; tm++) {
        int m = row0 + warp_m*64 + tm*16 + (lane >> 2);
        #pragma unroll
        for (int tn = 0; tn < 4; tn++) {
            int n = col0 + warp_n*32 + tn*8 + (lane & 3)*2;
            float b0 = bias[n], b1 = bias[n+1];
            float c0 = acc[tm][tn][0] + b0;
            float c1 = acc[tm][tn][1] + b1;
            float c2 = acc[tm][tn][2] + b0;
            float c3 = acc[tm][tn][3] + b1;
            if (GELU) { c0 = gelu_tanh(c0); c1 = gelu_tanh(c1); c2 = gelu_tanh(c2); c3 = gelu_tanh(c3); }
            float* p0 = g_scratch + coff + (long long)m*ldc + ccol + n;
            float* p1 = g_scratch + coff + (long long)(m+8)*ldc + ccol + n;
            p0[0] = c0; p0[1] = c1;
            p1[0] = c2; p1[1] = c3;
        }
    }
}

// ---------------- hyperbolic layernorm + to_manifold -------------------------
__global__ __launch_bounds__(256) void ln_kernel(const float* __restrict__ Xext, long long xoff,
                                                 const float* __restrict__ g, const float* __restrict__ bb,
                                                 long long ooff) {
    const float* X = Xext ? Xext : (g_scratch + xoff);
    float* O = g_scratch + ooff;
    __shared__ float sbuf[8];
    int row = blockIdx.x, tid = threadIdx.x;
    const float* xr = X + (long long)row*(ND+1) + 1;
    float v[4]; float s = 0.f;
    #pragma unroll
    for (int i = 0; i < 4; i++) { v[i] = xr[tid + i*256]; s += v[i]; }
    float mu = block_sum(s, sbuf) * (1.f/ND);
    float vs = 0.f;
    #pragma unroll
    for (int i = 0; i < 4; i++) { float d = v[i]-mu; vs += d*d; }
    float var = block_sum(vs, sbuf) * (1.f/ND);
    float rstd = rsqrtf(var + 1e-5f);
    float y[4]; float ss = 0.f;
    #pragma unroll
    for (int i = 0; i < 4; i++) {
        int c = tid + i*256;
        y[i] = (v[i]-mu)*rstd*g[c] + bb[c];
        ss += y[i]*y[i];
    }
    float tot = block_sum(ss, sbuf);
    float* orow = O + (long long)row*(ND+1);
    if (tid == 0) orow[0] = sqrtf(tot + 1.f);
    #pragma unroll
    for (int i = 0; i < 4; i++) orow[1 + tid + i*256] = y[i];
}

// ---------------- QKV post: RoPE + L2-normalize(q,k) + to_manifold -----------
__global__ __launch_bounds__(256) void qkvpost_kernel(const float* __restrict__ rc,
                                                      const float* __restrict__ rs) {
    int w    = (blockIdx.x << 3) + (threadIdx.x >> 5);
    int lane = threadIdx.x & 31;
    int h = w & (NH-1);
    int s = (w >> 4) & (NS-1);
    int b = w >> 14;
    const float* qkv = g_scratch + OFF_QKV + (long long)(b*NS + s)*3*ND + h*HD;
    float c0 = rc[s*32 + (lane>>1)],      s0 = rs[s*32 + (lane>>1)];
    float c1 = rc[s*32 + 16 + (lane>>1)], s1 = rs[s*32 + 16 + (lane>>1)];
    bool even = (lane & 1) == 0;
    long long dst = (long long)((b*NH + h)*NS + s)*(HD+1);

    #pragma unroll
    for (int which = 0; which < 2; which++) {
        float v0 = qkv[which*ND + lane], v1 = qkv[which*ND + lane + 32];
        float p0 = __shfl_xor_sync(0xffffffffu, v0, 1);
        float p1 = __shfl_xor_sync(0xffffffffu, v1, 1);
        float r0 = even ? (v0*c0 - p0*s0) : (p0*s0 + v0*c0);
        float r1 = even ? (v1*c1 - p1*s1) : (p1*s1 + v1*c1);
        float ssum = warp_sum(r0*r0 + r1*r1);
        float rn = rsqrtf(ssum + 1e-6f);
        r0 *= rn; r1 *= rn;
        float t = sqrtf(ssum*rn*rn + 1.f);
        float* dp = g_scratch + (which == 0 ? OFF_Q : OFF_K) + dst;
        if (lane == 0) dp[0] = t;
        dp[1+lane] = r0; dp[33+lane] = r1;
    }
    {
        float v0 = qkv[2*ND + lane], v1 = qkv[2*ND + lane + 32];
        float ssum = warp_sum(v0*v0 + v1*v1);
        float* dp = g_scratch + OFF_V + dst;
        if (lane == 0) dp[0] = sqrtf(ssum + 1.f);
        dp[1+lane] = v0; dp[33+lane] = v1;
    }
}

// ---------------- fused flash attention + project + concat -------------------
__global__ __launch_bounds__(256) void attn_kernel(const float* __restrict__ scale_p,
                                                   const float* __restrict__ bias_p) {
    __shared__ float Qs[64][65];
    __shared__ float KVs[65][68];
    int bh = blockIdx.y;
    int qt = blockIdx.x;
    int b = bh >> 4, h = bh & 15;
    float inv_scale = 1.f / *scale_p;
    float abias = *bias_p;
    int tid = threadIdx.x;
    int ql = tid >> 2, part = tid & 3;
    const float* Qb = g_scratch + OFF_Q + ((long long)bh*NS + qt*64)*65;
    const float* Kb = g_scratch + OFF_K + (long long)bh*NS*65;
    const float* Vb = g_scratch + OFF_V + (long long)bh*NS*65;
    for (int idx = tid; idx < 64*65; idx += 256) {
        int r = idx/65, c = idx%65;
        float v = Qb[idx];
        Qs[r][c] = (c == 0) ? -v : v;
    }
    float acc[65];
    #pragma unroll
    for (int d = 0; d < 65; d++) acc[d] = 0.f;
    float mi = -1e30f, li = 0.f;
    for (int kt = 0; kt < 16; kt++) {
        __syncthreads();
        for (int idx = tid; idx < 64*65; idx += 256) {
            int r = idx/65, c = idx%65;
            KVs[c][r] = Kb[(long long)kt*64*65 + idx];
        }
        __syncthreads();
        float sc[16];
        #pragma unroll
        for (int jj = 0; jj < 16; jj++) sc[jj] = 0.f;
        #pragma unroll 1
        for (int c = 0; c < 65; c++) {
            float qv = Qs[ql][c];
            #pragma unroll
            for (int jj = 0; jj < 16; jj++) sc[jj] += qv * KVs[c][part*16 + jj];
        }
        float tmax = -1e30f;
        #pragma unroll
        for (int jj = 0; jj < 16; jj++) {
            sc[jj] = (2.f + 2.f*sc[jj])*inv_scale + abias;
            tmax = fmaxf(tmax, sc[jj]);
        }
        tmax = fmaxf(tmax, __shfl_xor_sync(0xffffffffu, tmax, 1));
        tmax = fmaxf(tmax, __shfl_xor_sync(0xffffffffu, tmax, 2));
        float mnew = fmaxf(mi, tmax);
        float corr = __expf(mi - mnew);
        float ps = 0.f;
        #pragma unroll
        for (int jj = 0; jj < 16; jj++) { sc[jj] = __expf(sc[jj]-mnew); ps += sc[jj]; }
        ps += __shfl_xor_sync(0xffffffffu, ps, 1);
        ps += __shfl_xor_sync(0xffffffffu, ps, 2);
        li = li*corr + ps;
        mi = mnew;
        __syncthreads();
        for (int idx = tid; idx < 64*65; idx += 256) {
            int r = idx/65, c = idx%65;
            KVs[c][r] = Vb[(long long)kt*64*65 + idx];
        }
        __syncthreads();
        #pragma unroll
        for (int d = 0; d < 65; d++) {
            float a = acc[d]*corr;
            #pragma unroll
            for (int jj = 0; jj < 16; jj++) a += sc[jj]*KVs[d][part*16 + jj];
            acc[d] = a;
        }
    }
    #pragma unroll
    for (int d = 0; d < 65; d++) {
        acc[d] += __shfl_xor_sync(0xffffffffu, acc[d], 1);
        acc[d] += __shfl_xor_sync(0xffffffffu, acc[d], 2);
    }
    float invl = 1.f/li;
    float m0 = acc[0]*invl;
    float ssq = 0.f;
    #pragma unroll
    for (int d = 1; d < 65; d++) { float md = acc[d]*invl; ssq += md*md; }
    float inv = invl * rsqrtf(fmaxf(m0*m0 - ssq, 1e-6f));
    int sg = qt*64 + ql;
    float* dstp = g_scratch + OFF_CAT + (long long)(b*NS + sg)*(NH*(HD+1)) + h*(HD+1);
    for (int d = part; d < 65; d += 4) dstp[d] = acc[d]*inv;
}

// ---------------- residual + Lorentz projection ------------------------------
__global__ __launch_bounds__(256) void resproj_kernel(const float* __restrict__ Xext, long long xoff,
                                                      long long doff, const float* __restrict__ wptr,
                                                      float* Oext, long long ooff) {
    const float* X   = Xext ? Xext : (g_scratch + xoff);
    const float* Dsp = g_scratch + doff;
    float* O = Oext ? Oext : (g_scratch + ooff);
    __shared__ float sbuf[8];
    int row = blockIdx.x, tid = threadIdx.x;
    float w = *wptr;
    const float* dr = Dsp + (long long)row*ND;
    const float* xr = X + (long long)row*(ND+1);
    float d[4]; float s = 0.f;
    #pragma unroll
    for (int i = 0; i < 4; i++) { d[i] = dr[tid + i*256]; s += d[i]*d[i]; }
    float td = sqrtf(block_sum(s, sbuf) + 1.f);
    float z0 = xr[0] + w*td;
    float z[4]; float zs = 0.f;
    #pragma unroll
    for (int i = 0; i < 4; i++) { z[i] = xr[1 + tid + i*256] + w*d[i]; zs += z[i]*z[i]; }
    float tot = block_sum(zs, sbuf);
    float inv = rsqrtf(fmaxf(z0*z0 - tot, 1e-6f));
    float* orow = O + (long long)row*(ND+1);
    if (tid == 0) orow[0] = z0*inv;
    #pragma unroll
    for (int i = 0; i < 4; i++) orow[1 + tid + i*256] = z[i]*inv;
}

// ---------------- time component of gelu'd hidden ----------------------------
__global__ __launch_bounds__(256) void hgtime_kernel() {
    __shared__ float sbuf[8];
    int row = blockIdx.x, tid = threadIdx.x;
    float* hr = g_scratch + OFF_HG + (long long)row*(NFF+1);
    float s = 0.f;
    for (int c = tid; c < NFF; c += 256) { float v = hr[1+c]; s += v*v; }
    float tot = block_sum(s, sbuf);
    if (tid == 0) hr[0] = sqrtf(tot + 1.f);
}

// ---------------- launch ------------------------------------------------------
extern "C" void kernel_launch(void* const* d_in, const int* in_sizes, int n_in,
                              void* d_out, int out_size) {
    const float* x      = (const float*)d_in[0];
    const float* rc     = (const float*)d_in[1];
    const float* rs     = (const float*)d_in[2];
    const float* n1g    = (const float*)d_in[3];
    const float* n1b    = (const float*)d_in[4];
    const float* Wq     = (const float*)d_in[5];
    const float* bq     = (const float*)d_in[6];
    const float* Wk     = (const float*)d_in[7];
    const float* bk     = (const float*)d_in[8];
    const float* Wv     = (const float*)d_in[9];
    const float* bv     = (const float*)d_in[10];
    const float* ascale = (const float*)d_in[11];
    const float* abias  = (const float*)d_in[12];
    const float* Wo     = (const float*)d_in[13];
    const float* bo     = (const float*)d_in[14];
    const float* wr1    = (const float*)d_in[15];
    const float* n2g    = (const float*)d_in[16];
    const float* n2b    = (const float*)d_in[17];
    const float* W1     = (const float*)d_in[18];
    const float* b1     = (const float*)d_in[19];
    const float* W2     = (const float*)d_in[20];
    const float* b2     = (const float*)d_in[21];
    const float* wr2    = (const float*)d_in[22];
    float* out = (float*)d_out;

    const int DSM = 2*65536;
    cudaFuncSetAttribute(mma_gemm_kernel<false>, cudaFuncAttributeMaxDynamicSharedMemorySize, DSM);
    cudaFuncSetAttribute(mma_gemm_kernel<true>,  cudaFuncAttributeMaxDynamicSharedMemorySize, DSM);

    // ---- stage 1: LN1 + fused QKV GEMM ----
    ln_kernel<<<NR, 256>>>(x, 0, n1g, n1b, OFF_XN);
    convA_kernel<<<(int)((4096LL*1088 + 255)/256), 256>>>(OFF_XN, ND+1, 1088);
    convQKV_kernel<<<dim3(2, 34, 48), dim3(32, 8)>>>(Wq, Wk, Wv);
    biaspack_kernel<<<12, 256>>>(bq, bk, bv);
    mma_gemm_kernel<false><<<dim3(24, 32), 256, DSM>>>(nullptr, OFF_BQKV, OFF_QKV, 1088, 3072, 0);

    // ---- stage 2: RoPE/normalize + attention ----
    qkvpost_kernel<<<NB*NS*NH/8, 256>>>(rc, rs);
    attn_kernel<<<dim3(NS/64, NB*NH), 256>>>(ascale, abias);

    // ---- stage 3: Wo GEMM ----
    convA_kernel<<<(int)((4096LL*1088 + 255)/256), 256>>>(OFF_CAT, NH*(HD+1), 1088);
    convT_kernel<<<dim3(1024/32, 34), dim3(32, 8)>>>(Wo, NH*(HD+1), ND, 1088);
    mma_gemm_kernel<false><<<dim3(8, 32), 256, DSM>>>(bo, 0, OFF_AO, 1088, ND, 0);
    resproj_kernel<<<NR, 256>>>(x, 0, OFF_AO, wr1, nullptr, OFF_X1);

    // ---- stage 4: LN2 + W1 GEMM (+GELU) ----
    ln_kernel<<<NR, 256>>>(nullptr, OFF_X1, n2g, n2b, OFF_H2);
    convA_kernel<<<(int)((4096LL*1088 + 255)/256), 256>>>(OFF_H2, ND+1, 1088);
    convT_kernel<<<dim3(4096/32, 34), dim3(32, 8)>>>(W1, ND+1, NFF, 1088);
    mma_gemm_kernel<true><<<dim3(32, 32), 256, DSM>>>(b1, 0, OFF_HG, 1088, NFF+1, 1);
    hgtime_kernel<<<NR, 256>>>();

    // ---- stage 5: W2 GEMM + final residual/project ----
    convA_kernel<<<(int)((4096LL*4160 + 255)/256), 256>>>(OFF_HG, NFF+1, 4160);
    convT_kernel<<<dim3(1024/32, 130), dim3(32, 8)>>>(W2, NFF+1, ND, 4160);
    mma_gemm_kernel<false><<<dim3(8, 32), 256, DSM>>>(b2, 0, OFF_MLP, 4160, ND, 0);
    resproj_kernel<<<NR, 256>>>(nullptr, OFF_X1, OFF_MLP, wr2, out, 0);
}

// round 15
// speedup vs baseline: 4.1872x; 2.5886x over previous
#include <cuda_runtime.h>
#include <cuda_bf16.h>
#include <math.h>
#include <stdint.h>

#define NB 4
#define NS 1024
#define ND 1024
#define NH 16
#define HD 64
#define NFF 4096
#define NR (NB*NS)   // 4096 rows

// ---------------- fp32 scratch arena ----------------------------------------
constexpr long long OFF_XN   = 0;
constexpr long long OFF_BQKV = OFF_XN   + (long long)NR*(ND+1);
constexpr long long OFF_QKV  = OFF_BQKV + 3*ND;
constexpr long long OFF_Q    = OFF_QKV  + (long long)NR*3*ND;   // q0 [64bh][1024]
constexpr long long OFF_K    = OFF_Q    + (long long)NB*NH*NS*(HD+1);  // k0
constexpr long long OFF_V    = OFF_K    + (long long)NB*NH*NS*(HD+1);  // v0
constexpr long long OFF_CAT  = OFF_V    + (long long)NB*NH*NS*(HD+1);  // Vsp then cat
constexpr long long OFF_AO   = OFF_CAT  + (long long)NR*NH*(HD+1);
constexpr long long OFF_X1   = OFF_AO   + (long long)NR*ND;
constexpr long long OFF_H2   = OFF_X1   + (long long)NR*(ND+1);
constexpr long long OFF_HG   = OFF_H2   + (long long)NR*(ND+1);
constexpr long long OFF_MLP  = OFF_HG   + (long long)NR*(NFF+1);
constexpr long long SCRATCH_TOTAL = OFF_MLP + (long long)NR*ND;

__device__ __align__(256) float g_scratch[SCRATCH_TOTAL];

// ---------------- bf16 hi/lo arenas ------------------------------------------
constexpr long long A_ELE = 4096LL*4160;   // biggest A: HG (4096 x 4160)
constexpr long long B_ELE = 4096LL*1088;   // biggest B: W1^T (4096 x 1088)
__device__ __align__(256) __nv_bfloat16 g_AH[A_ELE];
__device__ __align__(256) __nv_bfloat16 g_AL[A_ELE];
__device__ __align__(256) __nv_bfloat16 g_BH[B_ELE];
__device__ __align__(256) __nv_bfloat16 g_BL[B_ELE];

// attention-phase aliases (regions free between QKV GEMM and Wo GEMM)
constexpr long long QK_LO = 8388608;   // lo-part offset inside g_AH / g_AL

// ---------------- PTX helpers ------------------------------------------------
__device__ __forceinline__ uint32_t smem_u32(const void* p) {
    uint32_t a;
    asm("{ .reg .u64 t; cvta.to.shared.u64 t, %1; cvt.u32.u64 %0, t; }" : "=r"(a) : "l"(p));
    return a;
}
#define CP_ASYNC16(dst, src) asm volatile("cp.async.cg.shared.global [%0], [%1], 16;" :: "r"(dst), "l"(src) : "memory")
#define CP_COMMIT()          asm volatile("cp.async.commit_group;" ::: "memory")
#define CP_WAIT(n)           asm volatile("cp.async.wait_group %0;" :: "n"(n) : "memory")

#define MMA_BF16(acc, a, b) \
    asm volatile("mma.sync.aligned.m16n8k16.row.col.f32.bf16.bf16.f32 " \
                 "{%0,%1,%2,%3},{%4,%5,%6,%7},{%8,%9},{%0,%1,%2,%3};" \
                 : "+f"((acc)[0]), "+f"((acc)[1]), "+f"((acc)[2]), "+f"((acc)[3]) \
                 : "r"((a)[0]), "r"((a)[1]), "r"((a)[2]), "r"((a)[3]), \
                   "r"((b)[0]), "r"((b)[1]))

__device__ __forceinline__ uint32_t SW(uint32_t a) { return a ^ ((a >> 3) & 0x70u); }
__device__ __forceinline__ uint32_t lds32(const char* base, uint32_t off) {
    return *(const uint32_t*)(base + off);
}

// ---------------- reductions -------------------------------------------------
__device__ __forceinline__ float warp_sum(float v) {
    v += __shfl_xor_sync(0xffffffffu, v, 16);
    v += __shfl_xor_sync(0xffffffffu, v, 8);
    v += __shfl_xor_sync(0xffffffffu, v, 4);
    v += __shfl_xor_sync(0xffffffffu, v, 2);
    v += __shfl_xor_sync(0xffffffffu, v, 1);
    return v;
}
__device__ __forceinline__ float block_sum(float v, float* sbuf) {
    __syncthreads();
    v = warp_sum(v);
    if ((threadIdx.x & 31) == 0) sbuf[threadIdx.x >> 5] = v;
    __syncthreads();
    if (threadIdx.x < 32) {
        float r = (threadIdx.x < 8) ? sbuf[threadIdx.x] : 0.f;
        r = warp_sum(r);
        if (threadIdx.x == 0) sbuf[0] = r;
    }
    __syncthreads();
    return sbuf[0];
}

// ---------------- A-side conversion: fp32 [4096,Ksrc] -> bf16 hi/lo [4096,Kp]
__global__ __launch_bounds__(256) void convA_kernel(long long srcoff, int Ksrc, int Kp) {
    long long idx = (long long)blockIdx.x*256 + threadIdx.x;
    long long tot = 4096LL*Kp;
    if (idx >= tot) return;
    int k = (int)(idx % Kp);
    long long m = idx / Kp;
    float v = (k < Ksrc) ? g_scratch[srcoff + m*Ksrc + k] : 0.f;
    __nv_bfloat16 hi = __float2bfloat16_rn(v);
    __nv_bfloat16 lo = __float2bfloat16_rn(v - __bfloat162float(hi));
    g_AH[idx] = hi; g_AL[idx] = lo;
}

// ---------------- B transpose+convert ----------------------------------------
__global__ __launch_bounds__(256) void convT_kernel(const float* __restrict__ src,
                                                    int Ksrc, int N, int Kp) {
    __shared__ float tile[32][33];
    int tx = threadIdx.x, ty = threadIdx.y;
    int n0 = blockIdx.x*32, k0 = blockIdx.y*32;
    #pragma unroll
    for (int i = 0; i < 4; i++) {
        int k = k0 + ty + i*8;
        tile[ty + i*8][tx] = (k < Ksrc) ? src[(long long)k*N + n0 + tx] : 0.f;
    }
    __syncthreads();
    #pragma unroll
    for (int i = 0; i < 4; i++) {
        int n = n0 + ty + i*8;
        int k = k0 + tx;
        float v = tile[tx][ty + i*8];
        __nv_bfloat16 hi = __float2bfloat16_rn(v);
        __nv_bfloat16 lo = __float2bfloat16_rn(v - __bfloat162float(hi));
        long long di = (long long)n*Kp + k;
        g_BH[di] = hi; g_BL[di] = lo;
    }
}

// ---------------- fused QKV weight transpose + bias pack ---------------------
__global__ __launch_bounds__(256) void convQKV_kernel(const float* __restrict__ Wq,
                                                      const float* __restrict__ Wk,
                                                      const float* __restrict__ Wv,
                                                      const float* __restrict__ bq,
                                                      const float* __restrict__ bk,
                                                      const float* __restrict__ bv) {
    __shared__ float tile[32][33];
    int tx = threadIdx.x, ty = threadIdx.y;
    int e0 = blockIdx.x*32, k0 = blockIdx.y*32;
    int z = blockIdx.z;
    int which = z >> 4, h = z & 15;
    const float* W = (which == 0) ? Wq : (which == 1 ? Wk : Wv);
    #pragma unroll
    for (int i = 0; i < 4; i++) {
        int k = k0 + ty + i*8;
        tile[ty + i*8][tx] = (k < ND+1) ? W[((long long)h*(ND+1) + k)*HD + e0 + tx] : 0.f;
    }
    __syncthreads();
    #pragma unroll
    for (int i = 0; i < 4; i++) {
        int e = e0 + ty + i*8;
        int k = k0 + tx;
        float v = tile[tx][ty + i*8];
        __nv_bfloat16 hi = __float2bfloat16_rn(v);
        __nv_bfloat16 lo = __float2bfloat16_rn(v - __bfloat162float(hi));
        int n = which*1024 + h*64 + e;
        long long di = (long long)n*1088 + k;
        g_BH[di] = hi; g_BL[di] = lo;
    }
    // fused bias pack (one block does it)
    if (blockIdx.x == 0 && blockIdx.y == 0 && blockIdx.z == 0) {
        int t = ty*32 + tx;
        for (int col = t; col < 3*ND; col += 256) {
            int w2 = col >> 10, rem = col & 1023;
            const float* bp = (w2 == 0) ? bq : (w2 == 1 ? bk : bv);
            g_scratch[OFF_BQKV + col] = bp[rem];
        }
    }
}

// ---------------- HMMA GEMM ---------------------------------------------------
__device__ __forceinline__ float gelu_tanh(float c) {
    float u = 0.7978845608028654f * (c + 0.044715f*c*c*c);
    return 0.5f * c * (1.f + tanhf(u));
}

template<bool GELU>
__global__ __launch_bounds__(256, 1)
void mma_gemm_kernel(const float* __restrict__ biasext, long long biasoff,
                     long long coff, int Kp, int ldc, int ccol) {
    extern __shared__ char sm[];
    const int tid = threadIdx.x;
    const int wid = tid >> 5, lane = tid & 31;
    const int warp_m = wid & 1, warp_n = wid >> 1;
    const int row0 = blockIdx.y * 128, col0 = blockIdx.x * 128;
    const uint32_t sbase = smem_u32(sm);

    float acc[4][4][4];
    #pragma unroll
    for (int i = 0; i < 4; i++)
        #pragma unroll
        for (int j = 0; j < 4; j++)
            #pragma unroll
            for (int q = 0; q < 4; q++) acc[i][j][q] = 0.f;

    const int nchunk = Kp >> 6;

    auto load_chunk = [&](int c, int bi) {
        const long long k0 = (long long)c << 6;
        uint32_t base = sbase + (uint32_t)bi * 65536u;
        #pragma unroll
        for (int t = 0; t < 4; t++) {
            int id = t*256 + tid;
            int r = id >> 3, s = id & 7;
            uint32_t sw = SW((uint32_t)(r*128 + s*16));
            long long ai = (long long)(row0 + r)*Kp + k0 + s*8;
            long long bj = (long long)(col0 + r)*Kp + k0 + s*8;
            CP_ASYNC16(base + sw,           g_AH + ai);
            CP_ASYNC16(base + 16384u + sw,  g_AL + ai);
            CP_ASYNC16(base + 32768u + sw,  g_BH + bj);
            CP_ASYNC16(base + 49152u + sw,  g_BL + bj);
        }
    };

    const uint32_t kmask = (uint32_t)(((lane >> 2) & 7) << 4);
    const uint32_t lrow  = (uint32_t)(lane >> 2);
    const uint32_t lkb   = (uint32_t)((lane & 3) * 4);

    auto compute = [&](int bi) {
        const char* Ah = sm + bi*65536;
        const char* Al = Ah + 16384;
        const char* Bh = Ah + 32768;
        const char* Bl = Ah + 49152;
        #pragma unroll
        for (int k16 = 0; k16 < 4; k16++) {
            uint32_t kb  = (uint32_t)(k16*32) + lkb;
            uint32_t ka0 = kb ^ kmask;
            uint32_t ka2 = (kb + 16u) ^ kmask;
            uint32_t ahf[4][4], alf[4][4], bhf[4][2], blf[4][2];
            #pragma unroll
            for (int tm = 0; tm < 4; tm++) {
                uint32_t r = (uint32_t)(warp_m*64 + tm*16) + lrow;
                uint32_t a0 = r*128 + ka0, a2 = r*128 + ka2;
                ahf[tm][0] = *(const uint32_t*)(Ah + a0);
                ahf[tm][1] = *(const uint32_t*)(Ah + a0 + 1024);
                ahf[tm][2] = *(const uint32_t*)(Ah + a2);
                ahf[tm][3] = *(const uint32_t*)(Ah + a2 + 1024);
                alf[tm][0] = *(const uint32_t*)(Al + a0);
                alf[tm][1] = *(const uint32_t*)(Al + a0 + 1024);
                alf[tm][2] = *(const uint32_t*)(Al + a2);
                alf[tm][3] = *(const uint32_t*)(Al + a2 + 1024);
            }
            #pragma unroll
            for (int tn = 0; tn < 4; tn++) {
                uint32_t n = (uint32_t)(warp_n*32 + tn*8) + lrow;
                uint32_t b0 = n*128 + ka0, b2 = n*128 + ka2;
                bhf[tn][0] = *(const uint32_t*)(Bh + b0);
                bhf[tn][1] = *(const uint32_t*)(Bh + b2);
                blf[tn][0] = *(const uint32_t*)(Bl + b0);
                blf[tn][1] = *(const uint32_t*)(Bl + b2);
            }
            #pragma unroll
            for (int tm = 0; tm < 4; tm++)
                #pragma unroll
                for (int tn = 0; tn < 4; tn++) {
                    MMA_BF16(acc[tm][tn], ahf[tm], bhf[tn]);
                    MMA_BF16(acc[tm][tn], ahf[tm], blf[tn]);
                    MMA_BF16(acc[tm][tn], alf[tm], bhf[tn]);
                }
        }
    };

    load_chunk(0, 0); CP_COMMIT();
    for (int c = 0; c < nchunk; c++) {
        int bi = c & 1;
        if (c + 1 < nchunk) { load_chunk(c + 1, bi ^ 1); CP_COMMIT(); CP_WAIT(1); }
        else                { CP_WAIT(0); }
        __syncthreads();
        compute(bi);
        __syncthreads();
    }

    const float* bias = biasext ? biasext : (g_scratch + biasoff);
    #pragma unroll
    for (int tm = 0; tm < 4; tm++) {
        int m = row0 + warp_m*64 + tm*16 + (lane >> 2);
        #pragma unroll
        for (int tn = 0; tn < 4; tn++) {
            int n = col0 + warp_n*32 + tn*8 + (lane & 3)*2;
            float b0 = bias[n], b1 = bias[n+1];
            float c0 = acc[tm][tn][0] + b0;
            float c1 = acc[tm][tn][1] + b1;
            float c2 = acc[tm][tn][2] + b0;
            float c3 = acc[tm][tn][3] + b1;
            if (GELU) { c0 = gelu_tanh(c0); c1 = gelu_tanh(c1); c2 = gelu_tanh(c2); c3 = gelu_tanh(c3); }
            float* p0 = g_scratch + coff + (long long)m*ldc + ccol + n;
            float* p1 = g_scratch + coff + (long long)(m+8)*ldc + ccol + n;
            p0[0] = c0; p0[1] = c1;
            p1[0] = c2; p1[1] = c3;
        }
    }
}

// ---------------- hyperbolic layernorm + to_manifold -------------------------
__global__ __launch_bounds__(256) void ln_kernel(const float* __restrict__ Xext, long long xoff,
                                                 const float* __restrict__ g, const float* __restrict__ bb,
                                                 long long ooff) {
    const float* X = Xext ? Xext : (g_scratch + xoff);
    float* O = g_scratch + ooff;
    __shared__ float sbuf[8];
    int row = blockIdx.x, tid = threadIdx.x;
    const float* xr = X + (long long)row*(ND+1) + 1;
    float v[4]; float s = 0.f;
    #pragma unroll
    for (int i = 0; i < 4; i++) { v[i] = xr[tid + i*256]; s += v[i]; }
    float mu = block_sum(s, sbuf) * (1.f/ND);
    float vs = 0.f;
    #pragma unroll
    for (int i = 0; i < 4; i++) { float d = v[i]-mu; vs += d*d; }
    float var = block_sum(vs, sbuf) * (1.f/ND);
    float rstd = rsqrtf(var + 1e-5f);
    float y[4]; float ss = 0.f;
    #pragma unroll
    for (int i = 0; i < 4; i++) {
        int c = tid + i*256;
        y[i] = (v[i]-mu)*rstd*g[c] + bb[c];
        ss += y[i]*y[i];
    }
    float tot = block_sum(ss, sbuf);
    float* orow = O + (long long)row*(ND+1);
    if (tid == 0) orow[0] = sqrtf(tot + 1.f);
    #pragma unroll
    for (int i = 0; i < 4; i++) orow[1 + tid + i*256] = y[i];
}

// ---------------- QKV post v2: RoPE + normalize, emit bf16 hi/lo -------------
__global__ __launch_bounds__(256) void qkvpost_kernel(const float* __restrict__ rc,
                                                      const float* __restrict__ rs) {
    int w    = (blockIdx.x << 3) + (threadIdx.x >> 5);
    int lane = threadIdx.x & 31;
    int h = w & (NH-1);
    int s = (w >> 4) & (NS-1);
    int b = w >> 14;
    int bh = b*NH + h;
    const float* qkv = g_scratch + OFF_QKV + (long long)(b*NS + s)*3*ND + h*HD;
    float c0 = rc[s*32 + (lane>>1)],      s0 = rs[s*32 + (lane>>1)];
    float c1 = rc[s*32 + 16 + (lane>>1)], s1 = rs[s*32 + 16 + (lane>>1)];
    bool even = (lane & 1) == 0;
    long long qi = ((long long)bh*NS + s)*64;

    #pragma unroll
    for (int which = 0; which < 2; which++) {
        float v0 = qkv[which*ND + lane], v1 = qkv[which*ND + lane + 32];
        float p0 = __shfl_xor_sync(0xffffffffu, v0, 1);
        float p1 = __shfl_xor_sync(0xffffffffu, v1, 1);
        float r0 = even ? (v0*c0 - p0*s0) : (p0*s0 + v0*c0);
        float r1 = even ? (v1*c1 - p1*s1) : (p1*s1 + v1*c1);
        float ssum = warp_sum(r0*r0 + r1*r1);
        float rn = rsqrtf(ssum + 1e-6f);
        r0 *= rn; r1 *= rn;
        float t = sqrtf(ssum*rn*rn + 1.f);
        __nv_bfloat16* bufh = (which == 0 ? g_AH : g_AL);
        __nv_bfloat16 h0 = __float2bfloat16_rn(r0);
        __nv_bfloat16 h1 = __float2bfloat16_rn(r1);
        bufh[qi + lane]          = h0;
        bufh[qi + lane + 32]     = h1;
        bufh[QK_LO + qi + lane]      = __float2bfloat16_rn(r0 - __bfloat162float(h0));
        bufh[QK_LO + qi + lane + 32] = __float2bfloat16_rn(r1 - __bfloat162float(h1));
        if (lane == 0) g_scratch[(which == 0 ? OFF_Q : OFF_K) + (long long)bh*NS + s] = t;
    }
    {
        float v0 = qkv[2*ND + lane], v1 = qkv[2*ND + lane + 32];
        float ssum = warp_sum(v0*v0 + v1*v1);
        g_scratch[OFF_CAT + qi + lane]      = v0;
        g_scratch[OFF_CAT + qi + lane + 32] = v1;
        if (lane == 0) g_scratch[OFF_V + (long long)bh*NS + s] = sqrtf(ssum + 1.f);
    }
}

// ---------------- V transpose: Vsp fp32 [bh][s][64] -> g_BH/g_BL [bh][d][1024]
__global__ __launch_bounds__(256) void convVT_kernel() {
    __shared__ float tile[32][33];
    int tx = threadIdx.x, ty = threadIdx.y;
    int s0 = blockIdx.x*32, d0 = blockIdx.y*32, bh = blockIdx.z;
    #pragma unroll
    for (int i = 0; i < 4; i++) {
        int s = s0 + ty + i*8;
        tile[ty + i*8][tx] = g_scratch[OFF_CAT + ((long long)bh*NS + s)*64 + d0 + tx];
    }
    __syncthreads();
    #pragma unroll
    for (int i = 0; i < 4; i++) {
        int d = d0 + ty + i*8;
        int s = s0 + tx;
        float v = tile[tx][ty + i*8];
        __nv_bfloat16 hi = __float2bfloat16_rn(v);
        long long o = ((long long)bh*64 + d)*NS + s;
        g_BH[o] = hi;
        g_BL[o] = __float2bfloat16_rn(v - __bfloat162float(hi));
    }
}

// ---------------- HMMA flash attention ---------------------------------------
// grid (8, 64): x = 128-query tile, y = bh. 8 warps: warp_m = wid&3, warp_n = wid>>2.
#define ATT_DSM 167936

__global__ __launch_bounds__(256, 1) void attn_mma_kernel(const float* __restrict__ scale_p) {
    extern __shared__ char sm[];
    const int tid = threadIdx.x;
    const int wid = tid >> 5, lane = tid & 31;
    const int warp_m = wid & 3, warp_n = wid >> 2;
    const int qt = blockIdx.x, bh = blockIdx.y;
    const int b = bh >> 4, h = bh & 15;
    const float esc = 2.f / __ldg(scale_p);
    const uint32_t sbase = smem_u32(sm);
    const uint32_t lrow = (uint32_t)(lane >> 2);
    const uint32_t lq4  = (uint32_t)((lane & 3) * 4);

    char* Qh = sm;          char* Ql = sm + 16384;
    char* Kh = sm + 32768;  char* Kl = sm + 49152;
    char* Vh = sm + 65536;  char* Vl = sm + 81920;
    char* Ph = sm + 98304;  char* Pl = sm + 131072;
    float* k0s = (float*)(sm + 163840);
    float* v0s = (float*)(sm + 164352);
    float* lred   = (float*)(sm + 164864);
    float* o0red  = (float*)(sm + 165888);
    float* ssqred = (float*)(sm + 166912);

    // ---- load Q tile (once) ----
    {
        long long qg = ((long long)bh*NS + qt*128)*64;
        #pragma unroll
        for (int t = 0; t < 4; t++) {
            int id = t*256 + tid;
            int r = id >> 3, s2 = id & 7;
            uint32_t sw = SW((uint32_t)(r*128 + s2*16));
            CP_ASYNC16(sbase + sw,          g_AH + qg + r*64 + s2*8);
            CP_ASYNC16(sbase + 16384u + sw, g_AH + QK_LO + qg + r*64 + s2*8);
        }
    }

    float q0v[2][2];
    #pragma unroll
    for (int tm = 0; tm < 2; tm++)
        #pragma unroll
        for (int sb = 0; sb < 2; sb++)
            q0v[tm][sb] = g_scratch[OFF_Q + (long long)bh*NS + qt*128 + warp_m*32 + tm*16 + sb*8 + lrow];

    float acco[2][4][4];
    #pragma unroll
    for (int i = 0; i < 2; i++)
        #pragma unroll
        for (int j = 0; j < 4; j++)
            #pragma unroll
            for (int q = 0; q < 4; q++) acco[i][j][q] = 0.f;
    float l_part[2][2]  = {{0.f,0.f},{0.f,0.f}};
    float o0_part[2][2] = {{0.f,0.f},{0.f,0.f}};

    for (int kt = 0; kt < 8; kt++) {
        __syncthreads();   // prior PV done before K/V overwrite
        {
            long long kg = ((long long)bh*NS + kt*128)*64;
            #pragma unroll
            for (int t = 0; t < 4; t++) {
                int id = t*256 + tid;
                int r = id >> 3, s2 = id & 7;
                uint32_t sw = SW((uint32_t)(r*128 + s2*16));
                CP_ASYNC16(sbase + 32768u + sw, g_AL + kg + r*64 + s2*8);
                CP_ASYNC16(sbase + 49152u + sw, g_AL + QK_LO + kg + r*64 + s2*8);
                long long vg = ((long long)bh*64 + (r>>1))*NS + kt*128 + (r&1)*64 + s2*8;
                CP_ASYNC16(sbase + 65536u + sw, g_BH + vg);
                CP_ASYNC16(sbase + 81920u + sw, g_BL + vg);
            }
            if (tid < 32)
                CP_ASYNC16(sbase + 163840u + tid*16, g_scratch + OFF_K + (long long)bh*NS + kt*128 + tid*4);
            else if (tid < 64)
                CP_ASYNC16(sbase + 164352u + (tid-32)*16, g_scratch + OFF_V + (long long)bh*NS + kt*128 + (tid-32)*4);
        }
        CP_COMMIT(); CP_WAIT(0);
        __syncthreads();

        // ---- S phase ----
        float accs[2][8][4];
        #pragma unroll
        for (int i = 0; i < 2; i++)
            #pragma unroll
            for (int j = 0; j < 8; j++)
                #pragma unroll
                for (int q = 0; q < 4; q++) accs[i][j][q] = 0.f;

        #pragma unroll
        for (int k16 = 0; k16 < 4; k16++) {
            uint32_t koff = (uint32_t)(k16*32) + lq4;
            uint32_t qah[2][4], qal[2][4], kbh[8][2], kbl[8][2];
            #pragma unroll
            for (int tm = 0; tm < 2; tm++) {
                uint32_t r = (uint32_t)(warp_m*32 + tm*16) + lrow;
                uint32_t a0 = SW(r*128 + koff), a1 = SW((r+8)*128 + koff);
                uint32_t a2 = SW(r*128 + koff + 16), a3 = SW((r+8)*128 + koff + 16);
                qah[tm][0] = lds32(Qh, a0); qah[tm][1] = lds32(Qh, a1);
                qah[tm][2] = lds32(Qh, a2); qah[tm][3] = lds32(Qh, a3);
                qal[tm][0] = lds32(Ql, a0); qal[tm][1] = lds32(Ql, a1);
                qal[tm][2] = lds32(Ql, a2); qal[tm][3] = lds32(Ql, a3);
            }
            #pragma unroll
            for (int tn = 0; tn < 8; tn++) {
                uint32_t n = (uint32_t)(warp_n*64 + tn*8) + lrow;
                uint32_t b0 = SW(n*128 + koff), b2 = SW(n*128 + koff + 16);
                kbh[tn][0] = lds32(Kh, b0); kbh[tn][1] = lds32(Kh, b2);
                kbl[tn][0] = lds32(Kl, b0); kbl[tn][1] = lds32(Kl, b2);
            }
            #pragma unroll
            for (int tm = 0; tm < 2; tm++)
                #pragma unroll
                for (int tn = 0; tn < 8; tn++) {
                    MMA_BF16(accs[tm][tn], qah[tm], kbh[tn]);
                    MMA_BF16(accs[tm][tn], qah[tm], kbl[tn]);
                    MMA_BF16(accs[tm][tn], qal[tm], kbh[tn]);
                }
        }

        // ---- fixup + exp + accumulate l/o0 + pack P ----
        #pragma unroll
        for (int tm = 0; tm < 2; tm++) {
            uint32_t r0 = (uint32_t)(warp_m*32 + tm*16) + lrow;
            uint32_t r1 = r0 + 8;
            float q00 = q0v[tm][0], q01 = q0v[tm][1];
            #pragma unroll
            for (int tn = 0; tn < 8; tn++) {
                int cl = warp_n*64 + tn*8 + (lane & 3)*2;
                float2 k0c = *(float2*)&k0s[cl];
                float2 v0c = *(float2*)&v0s[cl];
                float p00 = __expf(esc*(1.f + accs[tm][tn][0] - q00*k0c.x));
                float p01 = __expf(esc*(1.f + accs[tm][tn][1] - q00*k0c.y));
                float p10 = __expf(esc*(1.f + accs[tm][tn][2] - q01*k0c.x));
                float p11 = __expf(esc*(1.f + accs[tm][tn][3] - q01*k0c.y));
                l_part[tm][0]  += p00 + p01;       l_part[tm][1]  += p10 + p11;
                o0_part[tm][0] += p00*v0c.x + p01*v0c.y;
                o0_part[tm][1] += p10*v0c.x + p11*v0c.y;
                __nv_bfloat16 h00 = __float2bfloat16_rn(p00), h01 = __float2bfloat16_rn(p01);
                __nv_bfloat16 h10 = __float2bfloat16_rn(p10), h11 = __float2bfloat16_rn(p11);
                __nv_bfloat162 hh0; hh0.x = h00; hh0.y = h01;
                __nv_bfloat162 hh1; hh1.x = h10; hh1.y = h11;
                __nv_bfloat162 ll0; ll0.x = __float2bfloat16_rn(p00 - __bfloat162float(h00));
                                    ll0.y = __float2bfloat16_rn(p01 - __bfloat162float(h01));
                __nv_bfloat162 ll1; ll1.x = __float2bfloat16_rn(p10 - __bfloat162float(h10));
                                    ll1.y = __float2bfloat16_rn(p11 - __bfloat162float(h11));
                uint32_t colb = (uint32_t)((tn*8 + (lane & 3)*2) * 2);
                uint32_t o0a = SW((r0*2 + (uint32_t)warp_n)*128 + colb);
                uint32_t o1a = SW((r1*2 + (uint32_t)warp_n)*128 + colb);
                *(__nv_bfloat162*)(Ph + o0a) = hh0;
                *(__nv_bfloat162*)(Ph + o1a) = hh1;
                *(__nv_bfloat162*)(Pl + o0a) = ll0;
                *(__nv_bfloat162*)(Pl + o1a) = ll1;
            }
        }
        __syncthreads();   // P visible to all warps

        // ---- PV phase ----
        #pragma unroll
        for (int k16 = 0; k16 < 8; k16++) {
            uint32_t half = (uint32_t)(k16 >> 2);
            uint32_t koff = (uint32_t)((k16 & 3)*32) + lq4;
            uint32_t pah[2][4], pal[2][4], vbh[4][2], vbl[4][2];
            #pragma unroll
            for (int tm = 0; tm < 2; tm++) {
                uint32_t r = (uint32_t)(warp_m*32 + tm*16) + lrow;
                uint32_t a0 = SW(r*256 + half*128 + koff);
                uint32_t a1 = SW((r+8)*256 + half*128 + koff);
                uint32_t a2 = SW(r*256 + half*128 + koff + 16);
                uint32_t a3 = SW((r+8)*256 + half*128 + koff + 16);
                pah[tm][0] = lds32(Ph, a0); pah[tm][1] = lds32(Ph, a1);
                pah[tm][2] = lds32(Ph, a2); pah[tm][3] = lds32(Ph, a3);
                pal[tm][0] = lds32(Pl, a0); pal[tm][1] = lds32(Pl, a1);
                pal[tm][2] = lds32(Pl, a2); pal[tm][3] = lds32(Pl, a3);
            }
            #pragma unroll
            for (int tn = 0; tn < 4; tn++) {
                uint32_t d = (uint32_t)(warp_n*32 + tn*8) + lrow;
                uint32_t b0 = SW(d*256 + half*128 + koff);
                uint32_t b2 = SW(d*256 + half*128 + koff + 16);
                vbh[tn][0] = lds32(Vh, b0); vbh[tn][1] = lds32(Vh, b2);
                vbl[tn][0] = lds32(Vl, b0); vbl[tn][1] = lds32(Vl, b2);
            }
            #pragma unroll
            for (int tm = 0; tm < 2; tm++)
                #pragma unroll
                for (int tn = 0; tn < 4; tn++) {
                    MMA_BF16(acco[tm][tn], pah[tm], vbh[tn]);
                    MMA_BF16(acco[tm][tn], pah[tm], vbl[tn]);
                    MMA_BF16(acco[tm][tn], pal[tm], vbh[tn]);
                }
        }
    }

    // ---- reduce l and o0 across cols ----
    #pragma unroll
    for (int tm = 0; tm < 2; tm++)
        #pragma unroll
        for (int sb = 0; sb < 2; sb++) {
            float lv = l_part[tm][sb];
            lv += __shfl_xor_sync(0xffffffffu, lv, 1);
            lv += __shfl_xor_sync(0xffffffffu, lv, 2);
            float ov = o0_part[tm][sb];
            ov += __shfl_xor_sync(0xffffffffu, ov, 1);
            ov += __shfl_xor_sync(0xffffffffu, ov, 2);
            if ((lane & 3) == 0) {
                int row = warp_m*32 + tm*16 + sb*8 + (int)lrow;
                lred[warp_n*128 + row]  = lv;
                o0red[warp_n*128 + row] = ov;
            }
        }
    __syncthreads();

    float invl[2][2];
    #pragma unroll
    for (int tm = 0; tm < 2; tm++)
        #pragma unroll
        for (int sb = 0; sb < 2; sb++) {
            int row = warp_m*32 + tm*16 + sb*8 + (int)lrow;
            invl[tm][sb] = 1.f / (lred[row] + lred[128 + row]);
        }
    float ssq_part[2][2] = {{0.f,0.f},{0.f,0.f}};
    #pragma unroll
    for (int tm = 0; tm < 2; tm++)
        #pragma unroll
        for (int tn = 0; tn < 4; tn++) {
            float m0 = acco[tm][tn][0]*invl[tm][0];
            float m1 = acco[tm][tn][1]*invl[tm][0];
            float m2 = acco[tm][tn][2]*invl[tm][1];
            float m3 = acco[tm][tn][3]*invl[tm][1];
            acco[tm][tn][0] = m0; acco[tm][tn][1] = m1;
            acco[tm][tn][2] = m2; acco[tm][tn][3] = m3;
            ssq_part[tm][0] += m0*m0 + m1*m1;
            ssq_part[tm][1] += m2*m2 + m3*m3;
        }
    #pragma unroll
    for (int tm = 0; tm < 2; tm++)
        #pragma unroll
        for (int sb = 0; sb < 2; sb++) {
            float sv = ssq_part[tm][sb];
            sv += __shfl_xor_sync(0xffffffffu, sv, 1);
            sv += __shfl_xor_sync(0xffffffffu, sv, 2);
            if ((lane & 3) == 0) {
                int row = warp_m*32 + tm*16 + sb*8 + (int)lrow;
                ssqred[warp_n*128 + row] = sv;
            }
        }
    __syncthreads();

    // ---- project + write cat (scalar stores: 65-stride layout is odd/even mixed) ----
    float* cat = g_scratch + OFF_CAT;
    float invp[2][2];
    #pragma unroll
    for (int tm = 0; tm < 2; tm++)
        #pragma unroll
        for (int sb = 0; sb < 2; sb++) {
            int row = warp_m*32 + tm*16 + sb*8 + (int)lrow;
            float ssqt = ssqred[row] + ssqred[128 + row];
            float m0 = (o0red[row] + o0red[128 + row]) * invl[tm][sb];
            float ip = rsqrtf(fmaxf(m0*m0 - ssqt, 1e-6f));
            invp[tm][sb] = ip;
            if ((lane & 3) == 0 && warp_n == 0) {
                long long sg = (long long)(b*NS + qt*128 + row);
                cat[sg*1040 + h*65] = m0 * ip;
            }
        }
    #pragma unroll
    for (int tm = 0; tm < 2; tm++) {
        int r0 = warp_m*32 + tm*16 + (int)lrow;
        int r1 = r0 + 8;
        long long s0g = (long long)(b*NS + qt*128 + r0);
        long long s1g = (long long)(b*NS + qt*128 + r1);
        #pragma unroll
        for (int tn = 0; tn < 4; tn++) {
            int d0 = warp_n*32 + tn*8 + (lane & 3)*2;
            float* c0p = &cat[s0g*1040 + h*65 + 1 + d0];
            float* c1p = &cat[s1g*1040 + h*65 + 1 + d0];
            c0p[0] = acco[tm][tn][0]*invp[tm][0];
            c0p[1] = acco[tm][tn][1]*invp[tm][0];
            c1p[0] = acco[tm][tn][2]*invp[tm][1];
            c1p[1] = acco[tm][tn][3]*invp[tm][1];
        }
    }
}

// ---------------- residual + Lorentz projection ------------------------------
__global__ __launch_bounds__(256) void resproj_kernel(const float* __restrict__ Xext, long long xoff,
                                                      long long doff, const float* __restrict__ wptr,
                                                      float* Oext, long long ooff) {
    const float* X   = Xext ? Xext : (g_scratch + xoff);
    const float* Dsp = g_scratch + doff;
    float* O = Oext ? Oext : (g_scratch + ooff);
    __shared__ float sbuf[8];
    int row = blockIdx.x, tid = threadIdx.x;
    float w = *wptr;
    const float* dr = Dsp + (long long)row*ND;
    const float* xr = X + (long long)row*(ND+1);
    float d[4]; float s = 0.f;
    #pragma unroll
    for (int i = 0; i < 4; i++) { d[i] = dr[tid + i*256]; s += d[i]*d[i]; }
    float td = sqrtf(block_sum(s, sbuf) + 1.f);
    float z0 = xr[0] + w*td;
    float z[4]; float zs = 0.f;
    #pragma unroll
    for (int i = 0; i < 4; i++) { z[i] = xr[1 + tid + i*256] + w*d[i]; zs += z[i]*z[i]; }
    float tot = block_sum(zs, sbuf);
    float inv = rsqrtf(fmaxf(z0*z0 - tot, 1e-6f));
    float* orow = O + (long long)row*(ND+1);
    if (tid == 0) orow[0] = z0*inv;
    #pragma unroll
    for (int i = 0; i < 4; i++) orow[1 + tid + i*256] = z[i]*inv;
}

// ---------------- time component of gelu'd hidden ----------------------------
__global__ __launch_bounds__(256) void hgtime_kernel() {
    __shared__ float sbuf[8];
    int row = blockIdx.x, tid = threadIdx.x;
    float* hr = g_scratch + OFF_HG + (long long)row*(NFF+1);
    float s = 0.f;
    for (int c = tid; c < NFF; c += 256) { float v = hr[1+c]; s += v*v; }
    float tot = block_sum(s, sbuf);
    if (tid == 0) hr[0] = sqrtf(tot + 1.f);
}

// ---------------- launch ------------------------------------------------------
extern "C" void kernel_launch(void* const* d_in, const int* in_sizes, int n_in,
                              void* d_out, int out_size) {
    const float* x      = (const float*)d_in[0];
    const float* rc     = (const float*)d_in[1];
    const float* rs     = (const float*)d_in[2];
    const float* n1g    = (const float*)d_in[3];
    const float* n1b    = (const float*)d_in[4];
    const float* Wq     = (const float*)d_in[5];
    const float* bq     = (const float*)d_in[6];
    const float* Wk     = (const float*)d_in[7];
    const float* bk     = (const float*)d_in[8];
    const float* Wv     = (const float*)d_in[9];
    const float* bv     = (const float*)d_in[10];
    const float* ascale = (const float*)d_in[11];
    const float* Wo     = (const float*)d_in[13];
    const float* bo     = (const float*)d_in[14];
    const float* wr1    = (const float*)d_in[15];
    const float* n2g    = (const float*)d_in[16];
    const float* n2b    = (const float*)d_in[17];
    const float* W1     = (const float*)d_in[18];
    const float* b1     = (const float*)d_in[19];
    const float* W2     = (const float*)d_in[20];
    const float* b2     = (const float*)d_in[21];
    const float* wr2    = (const float*)d_in[22];
    float* out = (float*)d_out;

    const int DSM = 2*65536;
    cudaFuncSetAttribute(mma_gemm_kernel<false>, cudaFuncAttributeMaxDynamicSharedMemorySize, DSM);
    cudaFuncSetAttribute(mma_gemm_kernel<true>,  cudaFuncAttributeMaxDynamicSharedMemorySize, DSM);
    cudaFuncSetAttribute(attn_mma_kernel, cudaFuncAttributeMaxDynamicSharedMemorySize, ATT_DSM);

    // ---- stage 1: LN1 + fused QKV GEMM (GEMM is 4th launch -> gets profiled)
    ln_kernel<<<NR, 256>>>(x, 0, n1g, n1b, OFF_XN);
    convA_kernel<<<(int)((4096LL*1088 + 255)/256), 256>>>(OFF_XN, ND+1, 1088);
    convQKV_kernel<<<dim3(2, 34, 48), dim3(32, 8)>>>(Wq, Wk, Wv, bq, bk, bv);
    mma_gemm_kernel<false><<<dim3(24, 32), 256, DSM>>>(nullptr, OFF_BQKV, OFF_QKV, 1088, 3072, 0);

    // ---- stage 2: RoPE/normalize (bf16 emit) + V transpose + MMA attention
    qkvpost_kernel<<<NB*NS*NH/8, 256>>>(rc, rs);
    convVT_kernel<<<dim3(32, 2, 64), dim3(32, 8)>>>();
    attn_mma_kernel<<<dim3(8, 64), 256, ATT_DSM>>>(ascale);

    // ---- stage 3: Wo GEMM ----
    convA_kernel<<<(int)((4096LL*1088 + 255)/256), 256>>>(OFF_CAT, NH*(HD+1), 1088);
    convT_kernel<<<dim3(1024/32, 34), dim3(32, 8)>>>(Wo, NH*(HD+1), ND, 1088);
    mma_gemm_kernel<false><<<dim3(8, 32), 256, DSM>>>(bo, 0, OFF_AO, 1088, ND, 0);
    resproj_kernel<<<NR, 256>>>(x, 0, OFF_AO, wr1, nullptr, OFF_X1);

    // ---- stage 4: LN2 + W1 GEMM (+GELU) ----
    ln_kernel<<<NR, 256>>>(nullptr, OFF_X1, n2g, n2b, OFF_H2);
    convA_kernel<<<(int)((4096LL*1088 + 255)/256), 256>>>(OFF_H2, ND+1, 1088);
    convT_kernel<<<dim3(4096/32, 34), dim3(32, 8)>>>(W1, ND+1, NFF, 1088);
    mma_gemm_kernel<true><<<dim3(32, 32), 256, DSM>>>(b1, 0, OFF_HG, 1088, NFF+1, 1);
    hgtime_kernel<<<NR, 256>>>();

    // ---- stage 5: W2 GEMM + final residual/project ----
    convA_kernel<<<(int)((4096LL*4160 + 255)/256), 256>>>(OFF_HG, NFF+1, 4160);
    convT_kernel<<<dim3(1024/32, 130), dim3(32, 8)>>>(W2, NFF+1, ND, 4160);
    mma_gemm_kernel<false><<<dim3(8, 32), 256, DSM>>>(b2, 0, OFF_MLP, 4160, ND, 0);
    resproj_kernel<<<NR, 256>>>(nullptr, OFF_X1, OFF_MLP, wr2, out, 0);
}